// round 10
// baseline (speedup 1.0000x reference)
#include <cuda_runtime.h>
#include <cuda_fp16.h>
#include <cstdint>
#include <math.h>

#define SS 50
#define ROWS 4096
#define ITERS 2048           // 2 atoms / iter

// Scratch
__device__ float g_y[ROWS*128];
__device__ float g_ysum[ROWS*128];
__device__ int   g_nbr_is64;

// ---------------------------------------------------------------------------
__device__ __forceinline__ float sspf(float x) {
    float e = __expf(-fabsf(x));
    return fmaxf(x, 0.0f) + __log2f(1.0f + e) * 0.69314718055994531f - 0.69314718055994531f;
}
__device__ __forceinline__ uint32_t h2(float a, float b) {
    __half2 h = __floats2half2_rn(a, b);
    return *reinterpret_cast<uint32_t*>(&h);
}
__device__ __forceinline__ uint32_t tf32b(float x) {
    uint32_t r; asm("cvt.rna.tf32.f32 %0, %1;" : "=r"(r) : "f"(x)); return r;
}
// pair (i, i+4) adjacency position
__device__ __forceinline__ uint32_t pospair(uint32_t i) {
    return (i & ~7u) + ((i & 3u) << 1) + ((i >> 2) & 1u);
}
#define MMA_F16(d, a0, a1, a2, a3, b0, b1) \
    asm volatile("mma.sync.aligned.m16n8k16.row.col.f32.f16.f16.f32 " \
        "{%0,%1,%2,%3}, {%4,%5,%6,%7}, {%8,%9}, {%0,%1,%2,%3};" \
        : "+f"((d)[0]), "+f"((d)[1]), "+f"((d)[2]), "+f"((d)[3]) \
        : "r"(a0), "r"(a1), "r"(a2), "r"(a3), "r"(b0), "r"(b1))
#define MMA_TF32(d, a0, a1, a2, a3, b0, b1) \
    asm volatile("mma.sync.aligned.m16n8k8.row.col.f32.tf32.tf32.f32 " \
        "{%0,%1,%2,%3}, {%4,%5,%6,%7}, {%8,%9}, {%0,%1,%2,%3};" \
        : "+f"((d)[0]), "+f"((d)[1]), "+f"((d)[2]), "+f"((d)[3]) \
        : "r"(a0), "r"(a1), "r"(a2), "r"(a3), "r"(b0), "r"(b1))

// ---- wide staging helpers: one LDG.128, four tf32 STS -------------------
__device__ __forceinline__ void stage_row_f4(uint32_t* dst_row, uint32_t k, float4 v) {
    dst_row[pospair(k)]     = tf32b(v.x);
    dst_row[pospair(k + 1)] = tf32b(v.y);
    dst_row[pospair(k + 2)] = tf32b(v.z);
    dst_row[pospair(k + 3)] = tf32b(v.w);
}

// ---------------------------------------------------------------------------
// in2f: C[4096,128] = A @ B (tf32 mma). 128 blocks x 256 thr, 32 rows/block.
// Staging via LDG.128 (the round-9 scalar-LDG staging was latency-bound:
// issue=6.1%, 19us).  Block 0 also runs the parallel neighbor-dtype probe.
// ---------------------------------------------------------------------------
#define IN2F_SMEM ((32*136 + 128*136)*4)
__global__ void __launch_bounds__(256, 1)
in2f_tf32_kernel(const float* __restrict__ A, const float* __restrict__ Bw,
                 float* __restrict__ C, const int* __restrict__ nbr_raw)
{
    extern __shared__ uint32_t sm[];
    const int SB = 32*136;
    const int tid = threadIdx.x;
    const int m0  = blockIdx.x * 32;

    if (blockIdx.x == 0) {
        int nz = (tid < 128) ? (nbr_raw[2*tid + 1] != 0) : 0;
        int any = __syncthreads_or(nz);
        if (tid == 0) g_nbr_is64 = !any;
    }

    {
        const float4* A4 = (const float4*)(A + (size_t)m0 * 128);
        #pragma unroll
        for (int i4 = tid; i4 < 32*128/4; i4 += 256) {
            float4 v = A4[i4];
            int row = (4*i4) >> 7, k = (4*i4) & 127;
            stage_row_f4(sm + row*136, k, v);
        }
        const float4* B4 = (const float4*)Bw;
        #pragma unroll
        for (int i4 = tid; i4 < 128*128/4; i4 += 256) {
            float4 v = B4[i4];
            int k = (4*i4) >> 7, n = (4*i4) & 127;   // 4 consecutive n, same k
            const uint32_t pk = pospair((uint32_t)k);
            sm[SB + (n+0)*136 + pk] = tf32b(v.x);
            sm[SB + (n+1)*136 + pk] = tf32b(v.y);
            sm[SB + (n+2)*136 + pk] = tf32b(v.z);
            sm[SB + (n+3)*136 + pk] = tf32b(v.w);
        }
    }
    __syncthreads();

    const int lane = tid & 31, qr = lane >> 2, qc = lane & 3;
    const int w = tid >> 5;
    const int mt = w & 1;
    const int nb = (w >> 1) * 32;
    float acc[4][4];
    #pragma unroll
    for (int nt = 0; nt < 4; nt++)
        #pragma unroll
        for (int j = 0; j < 4; j++) acc[nt][j] = 0.0f;

    #pragma unroll
    for (int kt = 0; kt < 16; kt++) {
        const int ko = kt*8 + 2*qc;
        const uint2 aL = *(const uint2*)(sm + (16*mt + qr)*136 + ko);
        const uint2 aH = *(const uint2*)(sm + (16*mt + qr + 8)*136 + ko);
        #pragma unroll
        for (int nt = 0; nt < 4; nt++) {
            const uint2 b = *(const uint2*)(sm + SB + (nb + 8*nt + qr)*136 + ko);
            MMA_TF32(acc[nt], aL.x, aH.x, aL.y, aH.y, b.x, b.y);
        }
    }
    #pragma unroll
    for (int nt = 0; nt < 4; nt++) {
        const int c = nb + 8*nt + 2*qc;
        *(float2*)(C + (size_t)(m0 + 16*mt + qr)*128 + c)     = make_float2(acc[nt][0], acc[nt][1]);
        *(float2*)(C + (size_t)(m0 + 16*mt + qr + 8)*128 + c) = make_float2(acc[nt][2], acc[nt][3]);
    }
}

// ---------------------------------------------------------------------------
// Fused tail: out = ssp(A@B1 + b1) @ B2 + b2  (tf32 mma). 128 blocks x 256 thr.
// Same LDG.128 staging fix.
// ---------------------------------------------------------------------------
#define TAIL_SMEM ((32*136 + 2*128*136)*4)
__global__ void __launch_bounds__(256, 1)
tail_tf32_kernel(const float* __restrict__ A,
                 const float* __restrict__ B1, const float* __restrict__ b1,
                 const float* __restrict__ B2, const float* __restrict__ b2,
                 float* __restrict__ C)
{
    extern __shared__ uint32_t sm[];
    const int SB1 = 32*136, SB2 = SB1 + 128*136;
    const int tid = threadIdx.x;
    const int m0  = blockIdx.x * 32;
    {
        const float4* A4 = (const float4*)(A + (size_t)m0 * 128);
        #pragma unroll
        for (int i4 = tid; i4 < 32*128/4; i4 += 256) {
            float4 v = A4[i4];
            int row = (4*i4) >> 7, k = (4*i4) & 127;
            stage_row_f4(sm + row*136, k, v);
        }
        const float4* B14 = (const float4*)B1;
        const float4* B24 = (const float4*)B2;
        #pragma unroll
        for (int i4 = tid; i4 < 128*128/4; i4 += 256) {
            float4 v1 = B14[i4];
            float4 v2 = B24[i4];
            int k = (4*i4) >> 7, n = (4*i4) & 127;
            const uint32_t pk = pospair((uint32_t)k);
            sm[SB1 + (n+0)*136 + pk] = tf32b(v1.x);
            sm[SB1 + (n+1)*136 + pk] = tf32b(v1.y);
            sm[SB1 + (n+2)*136 + pk] = tf32b(v1.z);
            sm[SB1 + (n+3)*136 + pk] = tf32b(v1.w);
            sm[SB2 + (n+0)*136 + pk] = tf32b(v2.x);
            sm[SB2 + (n+1)*136 + pk] = tf32b(v2.y);
            sm[SB2 + (n+2)*136 + pk] = tf32b(v2.z);
            sm[SB2 + (n+3)*136 + pk] = tf32b(v2.w);
        }
    }
    __syncthreads();

    const int lane = tid & 31, qr = lane >> 2, qc = lane & 3;
    const int w = tid >> 5;
    const int mt = w & 1;
    const int nb = (w >> 1) * 32;

    float acc[4][4];
    #pragma unroll
    for (int nt = 0; nt < 4; nt++) {
        const float2 bb = *(const float2*)(b1 + nb + 8*nt + 2*qc);
        acc[nt][0] = bb.x; acc[nt][1] = bb.y; acc[nt][2] = bb.x; acc[nt][3] = bb.y;
    }
    #pragma unroll
    for (int kt = 0; kt < 16; kt++) {
        const int ko = kt*8 + 2*qc;
        const uint2 aL = *(const uint2*)(sm + (16*mt + qr)*136 + ko);
        const uint2 aH = *(const uint2*)(sm + (16*mt + qr + 8)*136 + ko);
        #pragma unroll
        for (int nt = 0; nt < 4; nt++) {
            const uint2 b = *(const uint2*)(sm + SB1 + (nb + 8*nt + qr)*136 + ko);
            MMA_TF32(acc[nt], aL.x, aH.x, aL.y, aH.y, b.x, b.y);
        }
    }
    __syncthreads();
    #pragma unroll
    for (int nt = 0; nt < 4; nt++) {
        const int c = nb + 8*nt + 2*qc;
        sm[(16*mt + qr)*136     + pospair(c)]   = tf32b(sspf(acc[nt][0]));
        sm[(16*mt + qr)*136     + pospair(c+1)] = tf32b(sspf(acc[nt][1]));
        sm[(16*mt + qr + 8)*136 + pospair(c)]   = tf32b(sspf(acc[nt][2]));
        sm[(16*mt + qr + 8)*136 + pospair(c+1)] = tf32b(sspf(acc[nt][3]));
    }
    __syncthreads();

    #pragma unroll
    for (int nt = 0; nt < 4; nt++) {
        const float2 bb = *(const float2*)(b2 + nb + 8*nt + 2*qc);
        acc[nt][0] = bb.x; acc[nt][1] = bb.y; acc[nt][2] = bb.x; acc[nt][3] = bb.y;
    }
    #pragma unroll
    for (int kt = 0; kt < 16; kt++) {
        const int ko = kt*8 + 2*qc;
        const uint2 aL = *(const uint2*)(sm + (16*mt + qr)*136 + ko);
        const uint2 aH = *(const uint2*)(sm + (16*mt + qr + 8)*136 + ko);
        #pragma unroll
        for (int nt = 0; nt < 4; nt++) {
            const uint2 b = *(const uint2*)(sm + SB2 + (nb + 8*nt + qr)*136 + ko);
            MMA_TF32(acc[nt], aL.x, aH.x, aL.y, aH.y, b.x, b.y);
        }
    }
    #pragma unroll
    for (int nt = 0; nt < 4; nt++) {
        const int c = nb + 8*nt + 2*qc;
        *(float2*)(C + (size_t)(m0 + 16*mt + qr)*128 + c)     = make_float2(acc[nt][0], acc[nt][1]);
        *(float2*)(C + (size_t)(m0 + 16*mt + qr + 8)*128 + c) = make_float2(acc[nt][2], acc[nt][3]);
    }
}

// ---------------------------------------------------------------------------
// Interaction: persistent fp16 mma, 148 blocks x 256 thr. (unchanged R9)
// Two independent 128-thread groups (wm = atom half). ONE barrier per iter:
// HHS double-buffered; epilogue's cw/nbr hoisted to registers pre-barrier.
// ---------------------------------------------------------------------------
#define W1S 0
#define A1S 5120
#define HHS 15360
#define CWS 33792
#define NBS 34048
#define MAIN_SMEM (34304*4)

__global__ void __launch_bounds__(256, 1)
interaction2_kernel(const float* __restrict__ r_ij,
                    const void*  __restrict__ nbrs_raw,
                    const float* __restrict__ mask,
                    const float* __restrict__ f_ij,
                    const float* __restrict__ Wf1, const float* __restrict__ bf1,
                    const float* __restrict__ Wf2, const float* __restrict__ bf2,
                    const float* __restrict__ y_in, float* __restrict__ ysum_out)
{
    extern __shared__ uint32_t smw[];
    float* sCw  = (float*)(smw + CWS);
    int*   sNbr = (int*)(smw + NBS);

    const int tid  = threadIdx.x;
    const int w    = tid >> 5;
    const int lane = tid & 31;
    const int qr   = lane >> 2;
    const int qc   = lane & 3;
    const int wm   = w & 1;          // group / atom-half: rows wm*64..+63
    const int wn   = w >> 1;         // col window: wn*32..+31
    const int gtid = wn*32 + lane;   // 0..127 within group
    const int is64 = g_nbr_is64;
    const int barid = wm + 1;

    // ---- Wf2 fragments: register-resident ----
    uint32_t w2f[8][4][2];
    #pragma unroll
    for (int kt = 0; kt < 8; kt++)
        #pragma unroll
        for (int nt = 0; nt < 4; nt++) {
            const int g  = wn*32 + 8*nt + qr;
            const int k0 = kt*16 + 2*qc;
            w2f[kt][nt][0] = h2(Wf2[k0*128 + g],     Wf2[(k0+1)*128 + g]);
            w2f[kt][nt][1] = h2(Wf2[(k0+8)*128 + g], Wf2[(k0+9)*128 + g]);
        }

    // ---- Wf1^T smem (fp16 paired, zero-pad K 50->64) ----
    for (int idx = tid; idx < 128*32; idx += 256) {
        int n = idx >> 5, k2 = idx & 31;
        float v0 = (2*k2     < SS) ? Wf1[(2*k2)*128 + n]   : 0.0f;
        float v1 = (2*k2 + 1 < SS) ? Wf1[(2*k2+1)*128 + n] : 0.0f;
        smw[W1S + n*40 + pospair(k2)] = h2(v0, v1);
    }
    // zero A1 pad (k2 25..31) in both buffers
    for (int idx = tid; idx < 2*128*7; idx += 256) {
        int b = idx / 896, r2 = idx % 896;
        int row = r2 / 7, k2 = 25 + r2 % 7;
        smw[A1S + b*5120 + row*40 + pospair(k2)] = 0u;
    }
    // ---- bootstrap iter0 into buf 0 (group-local rows) ----
    {
        const int it0 = blockIdx.x;
        const float* fb = f_ij + (size_t)it0*6400 + wm*64*SS;
        for (int idx = gtid; idx < 64*25; idx += 128) {
            int row = idx / 25, k2 = idx % 25;
            float2 v = *(const float2*)(fb + row*SS + 2*k2);
            smw[A1S + (wm*64 + row)*40 + pospair(k2)] = h2(v.x, v.y);
        }
        if (gtid < 64) {
            int rg = wm*64 + gtid;
            size_t off = (size_t)it0*128 + rg;
            float r = r_ij[off];
            float c = (r < 5.0f) ? 0.5f*(cosf(r*0.62831853071795864769f)+1.0f) : 0.0f;
            sCw[rg]  = c * mask[off];
            sNbr[rg] = is64 ? (int)((const long long*)nbrs_raw)[off]
                            : ((const int*)nbrs_raw)[off];
        }
    }
    __syncthreads();

    int p = 0;
    for (int it = blockIdx.x; it < ITERS; it += gridDim.x) {
        const int  nxt = it + gridDim.x;
        const bool hasNext = nxt < ITERS;

        // ---- prefetch next A1 half + cw/nbr into regs ----
        float2 pf[13];
        float nr = 0.f, nm = 0.f; int nn = 0;
        if (hasNext) {
            const float* fb = f_ij + (size_t)nxt*6400 + wm*64*SS;
            #pragma unroll
            for (int j = 0; j < 13; j++) {
                int idx = gtid + j*128;
                if (idx < 1600) {
                    int row = idx / 25, k2 = idx % 25;
                    pf[j] = *(const float2*)(fb + row*SS + 2*k2);
                }
            }
            if (gtid < 64) {
                size_t off = (size_t)nxt*128 + wm*64 + gtid;
                nr = r_ij[off]; nm = mask[off];
                nn = is64 ? (int)((const long long*)nbrs_raw)[off]
                          : ((const int*)nbrs_raw)[off];
            }
        }

        // ---- hoist THIS iter's cw / y-row pointers into registers ----
        float cwr[8]; const float* yrp[8];
        {
            const int base = ((2*it) >> 10) << 10;    // batch * 1024
            #pragma unroll
            for (int mt = 0; mt < 4; mt++)
                #pragma unroll
                for (int h = 0; h < 2; h++) {
                    const int rg = wm*64 + 16*mt + qr + 8*h;
                    cwr[2*mt+h] = sCw[p*128 + rg];
                    yrp[2*mt+h] = y_in + (size_t)(base + sNbr[p*128 + rg]) * 128;
                }
        }

        // ---- MMA1: acc = Fij @ Wf1 + bf1 (K=64 padded) ----
        float acc[4][4][4];
        #pragma unroll
        for (int nt = 0; nt < 4; nt++) {
            const float2 bb = *(const float2*)(bf1 + wn*32 + 8*nt + 2*qc);
            #pragma unroll
            for (int mt = 0; mt < 4; mt++) {
                acc[mt][nt][0] = bb.x; acc[mt][nt][1] = bb.y;
                acc[mt][nt][2] = bb.x; acc[mt][nt][3] = bb.y;
            }
        }
        #pragma unroll
        for (int kt = 0; kt < 4; kt++) {
            const int ko = kt*8 + 2*qc;
            uint2 aL[4], aH[4];
            #pragma unroll
            for (int mt = 0; mt < 4; mt++) {
                aL[mt] = *(const uint2*)(smw + A1S + p*5120 + (wm*64 + 16*mt + qr)*40 + ko);
                aH[mt] = *(const uint2*)(smw + A1S + p*5120 + (wm*64 + 16*mt + qr + 8)*40 + ko);
            }
            #pragma unroll
            for (int nt = 0; nt < 4; nt++) {
                const uint2 b = *(const uint2*)(smw + W1S + (wn*32 + 8*nt + qr)*40 + ko);
                #pragma unroll
                for (int mt = 0; mt < 4; mt++)
                    MMA_F16(acc[mt][nt], aL[mt].x, aH[mt].x, aL[mt].y, aH[mt].y, b.x, b.y);
            }
        }
        // ---- H = ssp(acc) -> HHS[p] ----
        #pragma unroll
        for (int mt = 0; mt < 4; mt++)
            #pragma unroll
            for (int nt = 0; nt < 4; nt++) {
                const uint32_t po = pospair((uint32_t)(wn*16 + 4*nt + qc));
                smw[HHS + p*9216 + (wm*64 + 16*mt + qr)*72 + po] =
                    h2(sspf(acc[mt][nt][0]), sspf(acc[mt][nt][1]));
                smw[HHS + p*9216 + (wm*64 + 16*mt + qr + 8)*72 + po] =
                    h2(sspf(acc[mt][nt][2]), sspf(acc[mt][nt][3]));
            }
        // ---- drain prefetch into buf p^1 ----
        if (hasNext) {
            #pragma unroll
            for (int j = 0; j < 13; j++) {
                int idx = gtid + j*128;
                if (idx < 1600) {
                    int row = idx / 25, k2 = idx % 25;
                    smw[A1S + (p^1)*5120 + (wm*64 + row)*40 + pospair(k2)] = h2(pf[j].x, pf[j].y);
                }
            }
            if (gtid < 64) {
                int rg = wm*64 + gtid;
                float c = (nr < 5.0f) ? 0.5f*(cosf(nr*0.62831853071795864769f)+1.0f) : 0.0f;
                sCw[(p^1)*128 + rg]  = c * nm;
                sNbr[(p^1)*128 + rg] = nn;
            }
        }
        asm volatile("bar.sync %0, %1;" :: "r"(barid), "r"(128) : "memory");  // H[p] ready

        // ---- MMA2: acc = H @ Wf2 + bf2 (K=128, W2 in regs) ----
        #pragma unroll
        for (int nt = 0; nt < 4; nt++) {
            const float2 bb = *(const float2*)(bf2 + wn*32 + 8*nt + 2*qc);
            #pragma unroll
            for (int mt = 0; mt < 4; mt++) {
                acc[mt][nt][0] = bb.x; acc[mt][nt][1] = bb.y;
                acc[mt][nt][2] = bb.x; acc[mt][nt][3] = bb.y;
            }
        }
        #pragma unroll
        for (int kt = 0; kt < 8; kt++) {
            const int ko = kt*8 + 2*qc;
            uint2 aL[4], aH[4];
            #pragma unroll
            for (int mt = 0; mt < 4; mt++) {
                aL[mt] = *(const uint2*)(smw + HHS + p*9216 + (wm*64 + 16*mt + qr)*72 + ko);
                aH[mt] = *(const uint2*)(smw + HHS + p*9216 + (wm*64 + 16*mt + qr + 8)*72 + ko);
            }
            #pragma unroll
            for (int nt = 0; nt < 4; nt++)
                #pragma unroll
                for (int mt = 0; mt < 4; mt++)
                    MMA_F16(acc[mt][nt], aL[mt].x, aH[mt].x, aL[mt].y, aH[mt].y,
                            w2f[kt][nt][0], w2f[kt][nt][1]);
        }

        // ---- epilogue: registers only (cwr/yrp); shfl reduce; STG ----
        {
            float s[4][2];
            #pragma unroll
            for (int nt = 0; nt < 4; nt++) { s[nt][0] = 0.f; s[nt][1] = 0.f; }
            #pragma unroll
            for (int mt = 0; mt < 4; mt++)
                #pragma unroll
                for (int h = 0; h < 2; h++) {
                    const float cw = cwr[2*mt+h];
                    const float* yr = yrp[2*mt+h];
                    #pragma unroll
                    for (int nt = 0; nt < 4; nt++) {
                        const float2 yv = *(const float2*)(yr + wn*32 + 8*nt + 2*qc);
                        s[nt][0] += acc[mt][nt][2*h]   * cw * yv.x;
                        s[nt][1] += acc[mt][nt][2*h+1] * cw * yv.y;
                    }
                }
            #pragma unroll
            for (int nt = 0; nt < 4; nt++) {
                #pragma unroll
                for (int m = 4; m <= 16; m <<= 1) {
                    s[nt][0] += __shfl_xor_sync(0xffffffffu, s[nt][0], m);
                    s[nt][1] += __shfl_xor_sync(0xffffffffu, s[nt][1], m);
                }
            }
            if (qr == 0) {
                #pragma unroll
                for (int nt = 0; nt < 4; nt++)
                    *(float2*)(ysum_out + (size_t)(2*it + wm)*128 + wn*32 + 8*nt + 2*qc) =
                        make_float2(s[nt][0], s[nt][1]);
            }
        }
        p ^= 1;   // no second barrier: HHS double-buffered, epi state in regs
    }
}

// ---------------------------------------------------------------------------
extern "C" void kernel_launch(void* const* d_in, const int* in_sizes, int n_in,
                              void* d_out, int out_size)
{
    const float* x       = (const float*)d_in[0];
    const float* r_ij    = (const float*)d_in[1];
    const void*  nbrs    = d_in[2];
    const float* mask    = (const float*)d_in[3];
    const float* f_ij    = (const float*)d_in[4];
    const float* Wf1     = (const float*)d_in[5];
    const float* bf1     = (const float*)d_in[6];
    const float* Wf2     = (const float*)d_in[7];
    const float* bf2     = (const float*)d_in[8];
    const float* W_in2f  = (const float*)d_in[9];
    const float* W_f2out = (const float*)d_in[10];
    const float* b_f2out = (const float*)d_in[11];
    const float* W_dense = (const float*)d_in[12];
    const float* b_dense = (const float*)d_in[13];
    float* out = (float*)d_out;

    float *yp, *ysump;
    cudaGetSymbolAddress((void**)&yp,    g_y);
    cudaGetSymbolAddress((void**)&ysump, g_ysum);

    cudaFuncSetAttribute(in2f_tf32_kernel, cudaFuncAttributeMaxDynamicSharedMemorySize, IN2F_SMEM);
    cudaFuncSetAttribute(tail_tf32_kernel, cudaFuncAttributeMaxDynamicSharedMemorySize, TAIL_SMEM);
    cudaFuncSetAttribute(interaction2_kernel, cudaFuncAttributeMaxDynamicSharedMemorySize, MAIN_SMEM);

    in2f_tf32_kernel<<<ROWS/32, 256, IN2F_SMEM>>>(x, W_in2f, yp, (const int*)nbrs);

    interaction2_kernel<<<148, 256, MAIN_SMEM>>>(r_ij, nbrs, mask, f_ij,
                                                 Wf1, bf1, Wf2, bf2, yp, ysump);

    tail_tf32_kernel<<<ROWS/32, 256, TAIL_SMEM>>>(ysump, W_f2out, b_f2out,
                                                  W_dense, b_dense, out);
}

// round 12
// speedup vs baseline: 1.1382x; 1.1382x over previous
#include <cuda_runtime.h>
#include <cuda_fp16.h>
#include <cstdint>
#include <math.h>

#define SS 50
#define ROWS 4096
#define ITERS 2048           // 2 atoms / iter

// Scratch
__device__ float g_y[ROWS*128];
__device__ float g_ysum[ROWS*128];
__device__ int   g_nbr_is64;

// one dynamic-shared symbol, one type, for ALL kernels in this TU
extern __shared__ uint32_t smw_dyn[];

// ---------------------------------------------------------------------------
__device__ __forceinline__ float sspf(float x) {
    float e = __expf(-fabsf(x));
    return fmaxf(x, 0.0f) + __log2f(1.0f + e) * 0.69314718055994531f - 0.69314718055994531f;
}
__device__ __forceinline__ uint32_t h2(float a, float b) {
    __half2 h = __floats2half2_rn(a, b);
    return *reinterpret_cast<uint32_t*>(&h);
}
__device__ __forceinline__ uint32_t tf32b(float x) {
    uint32_t r; asm("cvt.rna.tf32.f32 %0, %1;" : "=r"(r) : "f"(x)); return r;
}
// pair (i, i+4) adjacency position
__device__ __forceinline__ uint32_t pospair(uint32_t i) {
    return (i & ~7u) + ((i & 3u) << 1) + ((i >> 2) & 1u);
}
#define MMA_F16(d, a0, a1, a2, a3, b0, b1) \
    asm volatile("mma.sync.aligned.m16n8k16.row.col.f32.f16.f16.f32 " \
        "{%0,%1,%2,%3}, {%4,%5,%6,%7}, {%8,%9}, {%0,%1,%2,%3};" \
        : "+f"((d)[0]), "+f"((d)[1]), "+f"((d)[2]), "+f"((d)[3]) \
        : "r"(a0), "r"(a1), "r"(a2), "r"(a3), "r"(b0), "r"(b1))
#define MMA_TF32(d, a0, a1, a2, a3, b0, b1) \
    asm volatile("mma.sync.aligned.m16n8k8.row.col.f32.tf32.tf32.f32 " \
        "{%0,%1,%2,%3}, {%4,%5,%6,%7}, {%8,%9}, {%0,%1,%2,%3};" \
        : "+f"((d)[0]), "+f"((d)[1]), "+f"((d)[2]), "+f"((d)[3]) \
        : "r"(a0), "r"(a1), "r"(a2), "r"(a3), "r"(b0), "r"(b1))

// ---------------------------------------------------------------------------
// in2f: C[4096,128] = A @ B.  FFMA gemm (Round-6 measured 9.8us on this
// exact shape/traffic; every tf32-mma variant measured 15-19us).
// 128 blocks x 256 thr, 32 rows/block. Block 0 runs the parallel dtype probe.
// ---------------------------------------------------------------------------
#define IN2F_SMEM ((32*128 + 128*128)*4)
__global__ void __launch_bounds__(256, 1)
in2f_ffma_kernel(const float* __restrict__ A, const float* __restrict__ Bw,
                 float* __restrict__ C, const int* __restrict__ nbr_raw)
{
    float* sm = (float*)smw_dyn;
    float* sA = sm;             // 32*128
    float* sB = sm + 32*128;    // 128*128
    const int tid = threadIdx.x;
    const int m0  = blockIdx.x * 32;

    if (blockIdx.x == 0) {
        int nz = (tid < 128) ? (nbr_raw[2*tid + 1] != 0) : 0;
        int any = __syncthreads_or(nz);
        if (tid == 0) g_nbr_is64 = !any;
    }

    {
        const float4* Ag = (const float4*)(A + (size_t)m0 * 128);
        float4* sA4 = (float4*)sA;
        #pragma unroll
        for (int i = tid; i < 32*128/4; i += 256) sA4[i] = Ag[i];
        const float4* Bg = (const float4*)Bw;
        float4* sB4 = (float4*)sB;
        #pragma unroll
        for (int i = tid; i < 128*128/4; i += 256) sB4[i] = Bg[i];
    }
    __syncthreads();
    const int gcol = tid & 31, rg = tid >> 5;
    const int r0 = rg * 4;
    float acc[4][4];
    #pragma unroll
    for (int i = 0; i < 4; i++)
        #pragma unroll
        for (int j = 0; j < 4; j++) acc[i][j] = 0.0f;
    #pragma unroll 4
    for (int k = 0; k < 128; k++) {
        const float4 bv = ((const float4*)(sB + k*128))[gcol];
        #pragma unroll
        for (int i = 0; i < 4; i++) {
            const float a = sA[(r0 + i)*128 + k];
            acc[i][0] = fmaf(a, bv.x, acc[i][0]);
            acc[i][1] = fmaf(a, bv.y, acc[i][1]);
            acc[i][2] = fmaf(a, bv.z, acc[i][2]);
            acc[i][3] = fmaf(a, bv.w, acc[i][3]);
        }
    }
    #pragma unroll
    for (int i = 0; i < 4; i++)
        ((float4*)(C + (size_t)(m0 + r0 + i)*128))[gcol] =
            make_float4(acc[i][0], acc[i][1], acc[i][2], acc[i][3]);
}

// ---------------------------------------------------------------------------
// Fused tail: out = ssp(A@B1 + b1) @ B2 + b2  (tf32 mma). 128 blocks x 256 thr.
// Functionally identical to Round 9 (derived ~7.6us).
// ---------------------------------------------------------------------------
#define TAIL_SMEM ((32*136 + 2*128*136)*4)
__global__ void __launch_bounds__(256, 1)
tail_tf32_kernel(const float* __restrict__ A,
                 const float* __restrict__ B1, const float* __restrict__ b1,
                 const float* __restrict__ B2, const float* __restrict__ b2,
                 float* __restrict__ C)
{
    uint32_t* sm = smw_dyn;
    const int SB1 = 32*136, SB2 = SB1 + 128*136;
    const int tid = threadIdx.x;
    const int m0  = blockIdx.x * 32;
    for (int idx = tid; idx < 32*128; idx += 256) {
        int row = idx >> 7, k = idx & 127;
        sm[row*136 + pospair(k)] = tf32b(A[(size_t)(m0+row)*128 + k]);
    }
    for (int idx = tid; idx < 128*128; idx += 256) {
        int k = idx >> 7, n = idx & 127;
        sm[SB1 + n*136 + pospair(k)] = tf32b(B1[idx]);
        sm[SB2 + n*136 + pospair(k)] = tf32b(B2[idx]);
    }
    __syncthreads();

    const int lane = tid & 31, qr = lane >> 2, qc = lane & 3;
    const int w = tid >> 5;
    const int mt = w & 1;
    const int nb = (w >> 1) * 32;

    float acc[4][4];
    #pragma unroll
    for (int nt = 0; nt < 4; nt++) {
        const float2 bb = *(const float2*)(b1 + nb + 8*nt + 2*qc);
        acc[nt][0] = bb.x; acc[nt][1] = bb.y; acc[nt][2] = bb.x; acc[nt][3] = bb.y;
    }
    #pragma unroll
    for (int kt = 0; kt < 16; kt++) {
        const int ko = kt*8 + 2*qc;
        const uint2 aL = *(const uint2*)(sm + (16*mt + qr)*136 + ko);
        const uint2 aH = *(const uint2*)(sm + (16*mt + qr + 8)*136 + ko);
        #pragma unroll
        for (int nt = 0; nt < 4; nt++) {
            const uint2 b = *(const uint2*)(sm + SB1 + (nb + 8*nt + qr)*136 + ko);
            MMA_TF32(acc[nt], aL.x, aH.x, aL.y, aH.y, b.x, b.y);
        }
    }
    __syncthreads();
    #pragma unroll
    for (int nt = 0; nt < 4; nt++) {
        const int c = nb + 8*nt + 2*qc;
        sm[(16*mt + qr)*136     + pospair(c)]   = tf32b(sspf(acc[nt][0]));
        sm[(16*mt + qr)*136     + pospair(c+1)] = tf32b(sspf(acc[nt][1]));
        sm[(16*mt + qr + 8)*136 + pospair(c)]   = tf32b(sspf(acc[nt][2]));
        sm[(16*mt + qr + 8)*136 + pospair(c+1)] = tf32b(sspf(acc[nt][3]));
    }
    __syncthreads();

    #pragma unroll
    for (int nt = 0; nt < 4; nt++) {
        const float2 bb = *(const float2*)(b2 + nb + 8*nt + 2*qc);
        acc[nt][0] = bb.x; acc[nt][1] = bb.y; acc[nt][2] = bb.x; acc[nt][3] = bb.y;
    }
    #pragma unroll
    for (int kt = 0; kt < 16; kt++) {
        const int ko = kt*8 + 2*qc;
        const uint2 aL = *(const uint2*)(sm + (16*mt + qr)*136 + ko);
        const uint2 aH = *(const uint2*)(sm + (16*mt + qr + 8)*136 + ko);
        #pragma unroll
        for (int nt = 0; nt < 4; nt++) {
            const uint2 b = *(const uint2*)(sm + SB2 + (nb + 8*nt + qr)*136 + ko);
            MMA_TF32(acc[nt], aL.x, aH.x, aL.y, aH.y, b.x, b.y);
        }
    }
    #pragma unroll
    for (int nt = 0; nt < 4; nt++) {
        const int c = nb + 8*nt + 2*qc;
        *(float2*)(C + (size_t)(m0 + 16*mt + qr)*128 + c)     = make_float2(acc[nt][0], acc[nt][1]);
        *(float2*)(C + (size_t)(m0 + 16*mt + qr + 8)*128 + c) = make_float2(acc[nt][2], acc[nt][3]);
    }
}

// ---------------------------------------------------------------------------
// Interaction: persistent fp16 mma, 148 blocks x 256 thr. (unchanged R9)
// Two independent 128-thread groups (wm = atom half). ONE barrier per iter:
// HHS double-buffered; epilogue's cw/nbr hoisted to registers pre-barrier.
// ---------------------------------------------------------------------------
#define W1S 0
#define A1S 5120
#define HHS 15360
#define CWS 33792
#define NBS 34048
#define MAIN_SMEM (34304*4)

__global__ void __launch_bounds__(256, 1)
interaction2_kernel(const float* __restrict__ r_ij,
                    const void*  __restrict__ nbrs_raw,
                    const float* __restrict__ mask,
                    const float* __restrict__ f_ij,
                    const float* __restrict__ Wf1, const float* __restrict__ bf1,
                    const float* __restrict__ Wf2, const float* __restrict__ bf2,
                    const float* __restrict__ y_in, float* __restrict__ ysum_out)
{
    uint32_t* smw = smw_dyn;
    float* sCw  = (float*)(smw + CWS);
    int*   sNbr = (int*)(smw + NBS);

    const int tid  = threadIdx.x;
    const int w    = tid >> 5;
    const int lane = tid & 31;
    const int qr   = lane >> 2;
    const int qc   = lane & 3;
    const int wm   = w & 1;          // group / atom-half: rows wm*64..+63
    const int wn   = w >> 1;         // col window: wn*32..+31
    const int gtid = wn*32 + lane;   // 0..127 within group
    const int is64 = g_nbr_is64;
    const int barid = wm + 1;

    // ---- Wf2 fragments: register-resident ----
    uint32_t w2f[8][4][2];
    #pragma unroll
    for (int kt = 0; kt < 8; kt++)
        #pragma unroll
        for (int nt = 0; nt < 4; nt++) {
            const int g  = wn*32 + 8*nt + qr;
            const int k0 = kt*16 + 2*qc;
            w2f[kt][nt][0] = h2(Wf2[k0*128 + g],     Wf2[(k0+1)*128 + g]);
            w2f[kt][nt][1] = h2(Wf2[(k0+8)*128 + g], Wf2[(k0+9)*128 + g]);
        }

    // ---- Wf1^T smem (fp16 paired, zero-pad K 50->64) ----
    for (int idx = tid; idx < 128*32; idx += 256) {
        int n = idx >> 5, k2 = idx & 31;
        float v0 = (2*k2     < SS) ? Wf1[(2*k2)*128 + n]   : 0.0f;
        float v1 = (2*k2 + 1 < SS) ? Wf1[(2*k2+1)*128 + n] : 0.0f;
        smw[W1S + n*40 + pospair(k2)] = h2(v0, v1);
    }
    // zero A1 pad (k2 25..31) in both buffers
    for (int idx = tid; idx < 2*128*7; idx += 256) {
        int b = idx / 896, r2 = idx % 896;
        int row = r2 / 7, k2 = 25 + r2 % 7;
        smw[A1S + b*5120 + row*40 + pospair(k2)] = 0u;
    }
    // ---- bootstrap iter0 into buf 0 (group-local rows) ----
    {
        const int it0 = blockIdx.x;
        const float* fb = f_ij + (size_t)it0*6400 + wm*64*SS;
        for (int idx = gtid; idx < 64*25; idx += 128) {
            int row = idx / 25, k2 = idx % 25;
            float2 v = *(const float2*)(fb + row*SS + 2*k2);
            smw[A1S + (wm*64 + row)*40 + pospair(k2)] = h2(v.x, v.y);
        }
        if (gtid < 64) {
            int rg = wm*64 + gtid;
            size_t off = (size_t)it0*128 + rg;
            float r = r_ij[off];
            float c = (r < 5.0f) ? 0.5f*(cosf(r*0.62831853071795864769f)+1.0f) : 0.0f;
            sCw[rg]  = c * mask[off];
            sNbr[rg] = is64 ? (int)((const long long*)nbrs_raw)[off]
                            : ((const int*)nbrs_raw)[off];
        }
    }
    __syncthreads();

    int p = 0;
    for (int it = blockIdx.x; it < ITERS; it += gridDim.x) {
        const int  nxt = it + gridDim.x;
        const bool hasNext = nxt < ITERS;

        // ---- prefetch next A1 half + cw/nbr into regs ----
        float2 pf[13];
        float nr = 0.f, nm = 0.f; int nn = 0;
        if (hasNext) {
            const float* fb = f_ij + (size_t)nxt*6400 + wm*64*SS;
            #pragma unroll
            for (int j = 0; j < 13; j++) {
                int idx = gtid + j*128;
                if (idx < 1600) {
                    int row = idx / 25, k2 = idx % 25;
                    pf[j] = *(const float2*)(fb + row*SS + 2*k2);
                }
            }
            if (gtid < 64) {
                size_t off = (size_t)nxt*128 + wm*64 + gtid;
                nr = r_ij[off]; nm = mask[off];
                nn = is64 ? (int)((const long long*)nbrs_raw)[off]
                          : ((const int*)nbrs_raw)[off];
            }
        }

        // ---- hoist THIS iter's cw / y-row pointers into registers ----
        float cwr[8]; const float* yrp[8];
        {
            const int base = ((2*it) >> 10) << 10;    // batch * 1024
            #pragma unroll
            for (int mt = 0; mt < 4; mt++)
                #pragma unroll
                for (int h = 0; h < 2; h++) {
                    const int rg = wm*64 + 16*mt + qr + 8*h;
                    cwr[2*mt+h] = sCw[p*128 + rg];
                    yrp[2*mt+h] = y_in + (size_t)(base + sNbr[p*128 + rg]) * 128;
                }
        }

        // ---- MMA1: acc = Fij @ Wf1 + bf1 (K=64 padded) ----
        float acc[4][4][4];
        #pragma unroll
        for (int nt = 0; nt < 4; nt++) {
            const float2 bb = *(const float2*)(bf1 + wn*32 + 8*nt + 2*qc);
            #pragma unroll
            for (int mt = 0; mt < 4; mt++) {
                acc[mt][nt][0] = bb.x; acc[mt][nt][1] = bb.y;
                acc[mt][nt][2] = bb.x; acc[mt][nt][3] = bb.y;
            }
        }
        #pragma unroll
        for (int kt = 0; kt < 4; kt++) {
            const int ko = kt*8 + 2*qc;
            uint2 aL[4], aH[4];
            #pragma unroll
            for (int mt = 0; mt < 4; mt++) {
                aL[mt] = *(const uint2*)(smw + A1S + p*5120 + (wm*64 + 16*mt + qr)*40 + ko);
                aH[mt] = *(const uint2*)(smw + A1S + p*5120 + (wm*64 + 16*mt + qr + 8)*40 + ko);
            }
            #pragma unroll
            for (int nt = 0; nt < 4; nt++) {
                const uint2 b = *(const uint2*)(smw + W1S + (wn*32 + 8*nt + qr)*40 + ko);
                #pragma unroll
                for (int mt = 0; mt < 4; mt++)
                    MMA_F16(acc[mt][nt], aL[mt].x, aH[mt].x, aL[mt].y, aH[mt].y, b.x, b.y);
            }
        }
        // ---- H = ssp(acc) -> HHS[p] ----
        #pragma unroll
        for (int mt = 0; mt < 4; mt++)
            #pragma unroll
            for (int nt = 0; nt < 4; nt++) {
                const uint32_t po = pospair((uint32_t)(wn*16 + 4*nt + qc));
                smw[HHS + p*9216 + (wm*64 + 16*mt + qr)*72 + po] =
                    h2(sspf(acc[mt][nt][0]), sspf(acc[mt][nt][1]));
                smw[HHS + p*9216 + (wm*64 + 16*mt + qr + 8)*72 + po] =
                    h2(sspf(acc[mt][nt][2]), sspf(acc[mt][nt][3]));
            }
        // ---- drain prefetch into buf p^1 ----
        if (hasNext) {
            #pragma unroll
            for (int j = 0; j < 13; j++) {
                int idx = gtid + j*128;
                if (idx < 1600) {
                    int row = idx / 25, k2 = idx % 25;
                    smw[A1S + (p^1)*5120 + (wm*64 + row)*40 + pospair(k2)] = h2(pf[j].x, pf[j].y);
                }
            }
            if (gtid < 64) {
                int rg = wm*64 + gtid;
                float c = (nr < 5.0f) ? 0.5f*(cosf(nr*0.62831853071795864769f)+1.0f) : 0.0f;
                sCw[(p^1)*128 + rg]  = c * nm;
                sNbr[(p^1)*128 + rg] = nn;
            }
        }
        asm volatile("bar.sync %0, %1;" :: "r"(barid), "r"(128) : "memory");  // H[p] ready

        // ---- MMA2: acc = H @ Wf2 + bf2 (K=128, W2 in regs) ----
        #pragma unroll
        for (int nt = 0; nt < 4; nt++) {
            const float2 bb = *(const float2*)(bf2 + wn*32 + 8*nt + 2*qc);
            #pragma unroll
            for (int mt = 0; mt < 4; mt++) {
                acc[mt][nt][0] = bb.x; acc[mt][nt][1] = bb.y;
                acc[mt][nt][2] = bb.x; acc[mt][nt][3] = bb.y;
            }
        }
        #pragma unroll
        for (int kt = 0; kt < 8; kt++) {
            const int ko = kt*8 + 2*qc;
            uint2 aL[4], aH[4];
            #pragma unroll
            for (int mt = 0; mt < 4; mt++) {
                aL[mt] = *(const uint2*)(smw + HHS + p*9216 + (wm*64 + 16*mt + qr)*72 + ko);
                aH[mt] = *(const uint2*)(smw + HHS + p*9216 + (wm*64 + 16*mt + qr + 8)*72 + ko);
            }
            #pragma unroll
            for (int nt = 0; nt < 4; nt++)
                #pragma unroll
                for (int mt = 0; mt < 4; mt++)
                    MMA_F16(acc[mt][nt], aL[mt].x, aH[mt].x, aL[mt].y, aH[mt].y,
                            w2f[kt][nt][0], w2f[kt][nt][1]);
        }

        // ---- epilogue: registers only (cwr/yrp); shfl reduce; STG ----
        {
            float s[4][2];
            #pragma unroll
            for (int nt = 0; nt < 4; nt++) { s[nt][0] = 0.f; s[nt][1] = 0.f; }
            #pragma unroll
            for (int mt = 0; mt < 4; mt++)
                #pragma unroll
                for (int h = 0; h < 2; h++) {
                    const float cw = cwr[2*mt+h];
                    const float* yr = yrp[2*mt+h];
                    #pragma unroll
                    for (int nt = 0; nt < 4; nt++) {
                        const float2 yv = *(const float2*)(yr + wn*32 + 8*nt + 2*qc);
                        s[nt][0] += acc[mt][nt][2*h]   * cw * yv.x;
                        s[nt][1] += acc[mt][nt][2*h+1] * cw * yv.y;
                    }
                }
            #pragma unroll
            for (int nt = 0; nt < 4; nt++) {
                #pragma unroll
                for (int m = 4; m <= 16; m <<= 1) {
                    s[nt][0] += __shfl_xor_sync(0xffffffffu, s[nt][0], m);
                    s[nt][1] += __shfl_xor_sync(0xffffffffu, s[nt][1], m);
                }
            }
            if (qr == 0) {
                #pragma unroll
                for (int nt = 0; nt < 4; nt++)
                    *(float2*)(ysum_out + (size_t)(2*it + wm)*128 + wn*32 + 8*nt + 2*qc) =
                        make_float2(s[nt][0], s[nt][1]);
            }
        }
        p ^= 1;   // no second barrier: HHS double-buffered, epi state in regs
    }
}

// ---------------------------------------------------------------------------
extern "C" void kernel_launch(void* const* d_in, const int* in_sizes, int n_in,
                              void* d_out, int out_size)
{
    const float* x       = (const float*)d_in[0];
    const float* r_ij    = (const float*)d_in[1];
    const void*  nbrs    = d_in[2];
    const float* mask    = (const float*)d_in[3];
    const float* f_ij    = (const float*)d_in[4];
    const float* Wf1     = (const float*)d_in[5];
    const float* bf1     = (const float*)d_in[6];
    const float* Wf2     = (const float*)d_in[7];
    const float* bf2     = (const float*)d_in[8];
    const float* W_in2f  = (const float*)d_in[9];
    const float* W_f2out = (const float*)d_in[10];
    const float* b_f2out = (const float*)d_in[11];
    const float* W_dense = (const float*)d_in[12];
    const float* b_dense = (const float*)d_in[13];
    float* out = (float*)d_out;

    float *yp, *ysump;
    cudaGetSymbolAddress((void**)&yp,    g_y);
    cudaGetSymbolAddress((void**)&ysump, g_ysum);

    cudaFuncSetAttribute(in2f_ffma_kernel, cudaFuncAttributeMaxDynamicSharedMemorySize, IN2F_SMEM);
    cudaFuncSetAttribute(tail_tf32_kernel, cudaFuncAttributeMaxDynamicSharedMemorySize, TAIL_SMEM);
    cudaFuncSetAttribute(interaction2_kernel, cudaFuncAttributeMaxDynamicSharedMemorySize, MAIN_SMEM);

    in2f_ffma_kernel<<<ROWS/32, 256, IN2F_SMEM>>>(x, W_in2f, yp, (const int*)nbrs);

    interaction2_kernel<<<148, 256, MAIN_SMEM>>>(r_ij, nbrs, mask, f_ij,
                                                 Wf1, bf1, Wf2, bf2, yp, ysump);

    tail_tf32_kernel<<<ROWS/32, 256, TAIL_SMEM>>>(ysump, W_f2out, b_f2out,
                                                  W_dense, b_dense, out);
}

// round 13
// speedup vs baseline: 1.1392x; 1.0009x over previous
#include <cuda_runtime.h>
#include <cuda_fp16.h>
#include <cstdint>
#include <math.h>

#define SS 50
#define ROWS 4096
#define ITERS 2048           // 2 atoms / iter

// Scratch
__device__ float g_y[ROWS*128];
__device__ float g_ysum[ROWS*128];
__device__ int   g_nbr_is64;

// one dynamic-shared symbol, one type, for ALL kernels in this TU
extern __shared__ uint32_t smw_dyn[];

// ---------------------------------------------------------------------------
__device__ __forceinline__ float sspf(float x) {
    float e = __expf(-fabsf(x));
    return fmaxf(x, 0.0f) + __log2f(1.0f + e) * 0.69314718055994531f - 0.69314718055994531f;
}
__device__ __forceinline__ uint32_t h2(float a, float b) {
    __half2 h = __floats2half2_rn(a, b);
    return *reinterpret_cast<uint32_t*>(&h);
}
__device__ __forceinline__ uint32_t tf32b(float x) {
    uint32_t r; asm("cvt.rna.tf32.f32 %0, %1;" : "=r"(r) : "f"(x)); return r;
}
// pair (i, i+4) adjacency position
__device__ __forceinline__ uint32_t pospair(uint32_t i) {
    return (i & ~7u) + ((i & 3u) << 1) + ((i >> 2) & 1u);
}
#define MMA_F16(d, a0, a1, a2, a3, b0, b1) \
    asm volatile("mma.sync.aligned.m16n8k16.row.col.f32.f16.f16.f32 " \
        "{%0,%1,%2,%3}, {%4,%5,%6,%7}, {%8,%9}, {%0,%1,%2,%3};" \
        : "+f"((d)[0]), "+f"((d)[1]), "+f"((d)[2]), "+f"((d)[3]) \
        : "r"(a0), "r"(a1), "r"(a2), "r"(a3), "r"(b0), "r"(b1))
#define MMA_TF32(d, a0, a1, a2, a3, b0, b1) \
    asm volatile("mma.sync.aligned.m16n8k8.row.col.f32.tf32.tf32.f32 " \
        "{%0,%1,%2,%3}, {%4,%5,%6,%7}, {%8,%9}, {%0,%1,%2,%3};" \
        : "+f"((d)[0]), "+f"((d)[1]), "+f"((d)[2]), "+f"((d)[3]) \
        : "r"(a0), "r"(a1), "r"(a2), "r"(a3), "r"(b0), "r"(b1))

// ---------------------------------------------------------------------------
// in2f: C[4096,128] = A @ B.  FFMA gemm (measured 9.4us).
// 128 blocks x 256 thr, 32 rows/block. Block 0 runs the parallel dtype probe.
// ---------------------------------------------------------------------------
#define IN2F_SMEM ((32*128 + 128*128)*4)
__global__ void __launch_bounds__(256, 1)
in2f_ffma_kernel(const float* __restrict__ A, const float* __restrict__ Bw,
                 float* __restrict__ C, const int* __restrict__ nbr_raw)
{
    float* sm = (float*)smw_dyn;
    float* sA = sm;             // 32*128
    float* sB = sm + 32*128;    // 128*128
    const int tid = threadIdx.x;
    const int m0  = blockIdx.x * 32;

    if (blockIdx.x == 0) {
        int nz = (tid < 128) ? (nbr_raw[2*tid + 1] != 0) : 0;
        int any = __syncthreads_or(nz);
        if (tid == 0) g_nbr_is64 = !any;
    }

    {
        const float4* Ag = (const float4*)(A + (size_t)m0 * 128);
        float4* sA4 = (float4*)sA;
        #pragma unroll
        for (int i = tid; i < 32*128/4; i += 256) sA4[i] = Ag[i];
        const float4* Bg = (const float4*)Bw;
        float4* sB4 = (float4*)sB;
        #pragma unroll
        for (int i = tid; i < 128*128/4; i += 256) sB4[i] = Bg[i];
    }
    __syncthreads();
    const int gcol = tid & 31, rg = tid >> 5;
    const int r0 = rg * 4;
    float acc[4][4];
    #pragma unroll
    for (int i = 0; i < 4; i++)
        #pragma unroll
        for (int j = 0; j < 4; j++) acc[i][j] = 0.0f;
    #pragma unroll 4
    for (int k = 0; k < 128; k++) {
        const float4 bv = ((const float4*)(sB + k*128))[gcol];
        #pragma unroll
        for (int i = 0; i < 4; i++) {
            const float a = sA[(r0 + i)*128 + k];
            acc[i][0] = fmaf(a, bv.x, acc[i][0]);
            acc[i][1] = fmaf(a, bv.y, acc[i][1]);
            acc[i][2] = fmaf(a, bv.z, acc[i][2]);
            acc[i][3] = fmaf(a, bv.w, acc[i][3]);
        }
    }
    #pragma unroll
    for (int i = 0; i < 4; i++)
        ((float4*)(C + (size_t)(m0 + r0 + i)*128))[gcol] =
            make_float4(acc[i][0], acc[i][1], acc[i][2], acc[i][3]);
}

// ---------------------------------------------------------------------------
// Fused tail: out = ssp(A@B1 + b1) @ B2 + b2  (tf32 mma). 128 blocks x 256 thr.
// ---------------------------------------------------------------------------
#define TAIL_SMEM ((32*136 + 2*128*136)*4)
__global__ void __launch_bounds__(256, 1)
tail_tf32_kernel(const float* __restrict__ A,
                 const float* __restrict__ B1, const float* __restrict__ b1,
                 const float* __restrict__ B2, const float* __restrict__ b2,
                 float* __restrict__ C)
{
    uint32_t* sm = smw_dyn;
    const int SB1 = 32*136, SB2 = SB1 + 128*136;
    const int tid = threadIdx.x;
    const int m0  = blockIdx.x * 32;
    for (int idx = tid; idx < 32*128; idx += 256) {
        int row = idx >> 7, k = idx & 127;
        sm[row*136 + pospair(k)] = tf32b(A[(size_t)(m0+row)*128 + k]);
    }
    for (int idx = tid; idx < 128*128; idx += 256) {
        int k = idx >> 7, n = idx & 127;
        sm[SB1 + n*136 + pospair(k)] = tf32b(B1[idx]);
        sm[SB2 + n*136 + pospair(k)] = tf32b(B2[idx]);
    }
    __syncthreads();

    const int lane = tid & 31, qr = lane >> 2, qc = lane & 3;
    const int w = tid >> 5;
    const int mt = w & 1;
    const int nb = (w >> 1) * 32;

    float acc[4][4];
    #pragma unroll
    for (int nt = 0; nt < 4; nt++) {
        const float2 bb = *(const float2*)(b1 + nb + 8*nt + 2*qc);
        acc[nt][0] = bb.x; acc[nt][1] = bb.y; acc[nt][2] = bb.x; acc[nt][3] = bb.y;
    }
    #pragma unroll
    for (int kt = 0; kt < 16; kt++) {
        const int ko = kt*8 + 2*qc;
        const uint2 aL = *(const uint2*)(sm + (16*mt + qr)*136 + ko);
        const uint2 aH = *(const uint2*)(sm + (16*mt + qr + 8)*136 + ko);
        #pragma unroll
        for (int nt = 0; nt < 4; nt++) {
            const uint2 b = *(const uint2*)(sm + SB1 + (nb + 8*nt + qr)*136 + ko);
            MMA_TF32(acc[nt], aL.x, aH.x, aL.y, aH.y, b.x, b.y);
        }
    }
    __syncthreads();
    #pragma unroll
    for (int nt = 0; nt < 4; nt++) {
        const int c = nb + 8*nt + 2*qc;
        sm[(16*mt + qr)*136     + pospair(c)]   = tf32b(sspf(acc[nt][0]));
        sm[(16*mt + qr)*136     + pospair(c+1)] = tf32b(sspf(acc[nt][1]));
        sm[(16*mt + qr + 8)*136 + pospair(c)]   = tf32b(sspf(acc[nt][2]));
        sm[(16*mt + qr + 8)*136 + pospair(c+1)] = tf32b(sspf(acc[nt][3]));
    }
    __syncthreads();

    #pragma unroll
    for (int nt = 0; nt < 4; nt++) {
        const float2 bb = *(const float2*)(b2 + nb + 8*nt + 2*qc);
        acc[nt][0] = bb.x; acc[nt][1] = bb.y; acc[nt][2] = bb.x; acc[nt][3] = bb.y;
    }
    #pragma unroll
    for (int kt = 0; kt < 16; kt++) {
        const int ko = kt*8 + 2*qc;
        const uint2 aL = *(const uint2*)(sm + (16*mt + qr)*136 + ko);
        const uint2 aH = *(const uint2*)(sm + (16*mt + qr + 8)*136 + ko);
        #pragma unroll
        for (int nt = 0; nt < 4; nt++) {
            const uint2 b = *(const uint2*)(sm + SB2 + (nb + 8*nt + qr)*136 + ko);
            MMA_TF32(acc[nt], aL.x, aH.x, aL.y, aH.y, b.x, b.y);
        }
    }
    #pragma unroll
    for (int nt = 0; nt < 4; nt++) {
        const int c = nb + 8*nt + 2*qc;
        *(float2*)(C + (size_t)(m0 + 16*mt + qr)*128 + c)     = make_float2(acc[nt][0], acc[nt][1]);
        *(float2*)(C + (size_t)(m0 + 16*mt + qr + 8)*128 + c) = make_float2(acc[nt][2], acc[nt][3]);
    }
}

// ---------------------------------------------------------------------------
// Interaction: persistent fp16 mma, 148 blocks x 256 thr.
// R13 CHANGE: group split wm = w>>2 (warps 0-3 vs 4-7). Each SMSP now holds
// ONE warp from each group, so when one group barriers/does ssp, the other
// group's HMMAs keep that SMSP's tensor pipe busy. (Old wm = w&1 put both
// warps of the SAME group on each SMSP -> pipe idled during barrier skew.)
// ---------------------------------------------------------------------------
#define W1S 0
#define A1S 5120
#define HHS 15360
#define CWS 33792
#define NBS 34048
#define MAIN_SMEM (34304*4)

__global__ void __launch_bounds__(256, 1)
interaction2_kernel(const float* __restrict__ r_ij,
                    const void*  __restrict__ nbrs_raw,
                    const float* __restrict__ mask,
                    const float* __restrict__ f_ij,
                    const float* __restrict__ Wf1, const float* __restrict__ bf1,
                    const float* __restrict__ Wf2, const float* __restrict__ bf2,
                    const float* __restrict__ y_in, float* __restrict__ ysum_out)
{
    uint32_t* smw = smw_dyn;
    float* sCw  = (float*)(smw + CWS);
    int*   sNbr = (int*)(smw + NBS);

    const int tid  = threadIdx.x;
    const int w    = tid >> 5;
    const int lane = tid & 31;
    const int qr   = lane >> 2;
    const int qc   = lane & 3;
    const int wm   = w >> 2;         // group / atom-half: warps 0-3 vs 4-7
    const int wn   = w & 3;          // col window: wn*32..+31
    const int gtid = wn*32 + lane;   // 0..127 within group
    const int is64 = g_nbr_is64;
    const int barid = wm + 1;

    // ---- Wf2 fragments: register-resident ----
    uint32_t w2f[8][4][2];
    #pragma unroll
    for (int kt = 0; kt < 8; kt++)
        #pragma unroll
        for (int nt = 0; nt < 4; nt++) {
            const int g  = wn*32 + 8*nt + qr;
            const int k0 = kt*16 + 2*qc;
            w2f[kt][nt][0] = h2(Wf2[k0*128 + g],     Wf2[(k0+1)*128 + g]);
            w2f[kt][nt][1] = h2(Wf2[(k0+8)*128 + g], Wf2[(k0+9)*128 + g]);
        }

    // ---- Wf1^T smem (fp16 paired, zero-pad K 50->64) ----
    for (int idx = tid; idx < 128*32; idx += 256) {
        int n = idx >> 5, k2 = idx & 31;
        float v0 = (2*k2     < SS) ? Wf1[(2*k2)*128 + n]   : 0.0f;
        float v1 = (2*k2 + 1 < SS) ? Wf1[(2*k2+1)*128 + n] : 0.0f;
        smw[W1S + n*40 + pospair(k2)] = h2(v0, v1);
    }
    // zero A1 pad (k2 25..31) in both buffers
    for (int idx = tid; idx < 2*128*7; idx += 256) {
        int b = idx / 896, r2 = idx % 896;
        int row = r2 / 7, k2 = 25 + r2 % 7;
        smw[A1S + b*5120 + row*40 + pospair(k2)] = 0u;
    }
    // ---- bootstrap iter0 into buf 0 (group-local rows) ----
    {
        const int it0 = blockIdx.x;
        const float* fb = f_ij + (size_t)it0*6400 + wm*64*SS;
        for (int idx = gtid; idx < 64*25; idx += 128) {
            int row = idx / 25, k2 = idx % 25;
            float2 v = *(const float2*)(fb + row*SS + 2*k2);
            smw[A1S + (wm*64 + row)*40 + pospair(k2)] = h2(v.x, v.y);
        }
        if (gtid < 64) {
            int rg = wm*64 + gtid;
            size_t off = (size_t)it0*128 + rg;
            float r = r_ij[off];
            float c = (r < 5.0f) ? 0.5f*(cosf(r*0.62831853071795864769f)+1.0f) : 0.0f;
            sCw[rg]  = c * mask[off];
            sNbr[rg] = is64 ? (int)((const long long*)nbrs_raw)[off]
                            : ((const int*)nbrs_raw)[off];
        }
    }
    __syncthreads();

    int p = 0;
    for (int it = blockIdx.x; it < ITERS; it += gridDim.x) {
        const int  nxt = it + gridDim.x;
        const bool hasNext = nxt < ITERS;

        // ---- prefetch next A1 half + cw/nbr into regs ----
        float2 pf[13];
        float nr = 0.f, nm = 0.f; int nn = 0;
        if (hasNext) {
            const float* fb = f_ij + (size_t)nxt*6400 + wm*64*SS;
            #pragma unroll
            for (int j = 0; j < 13; j++) {
                int idx = gtid + j*128;
                if (idx < 1600) {
                    int row = idx / 25, k2 = idx % 25;
                    pf[j] = *(const float2*)(fb + row*SS + 2*k2);
                }
            }
            if (gtid < 64) {
                size_t off = (size_t)nxt*128 + wm*64 + gtid;
                nr = r_ij[off]; nm = mask[off];
                nn = is64 ? (int)((const long long*)nbrs_raw)[off]
                          : ((const int*)nbrs_raw)[off];
            }
        }

        // ---- hoist THIS iter's cw / y-row pointers into registers ----
        float cwr[8]; const float* yrp[8];
        {
            const int base = ((2*it) >> 10) << 10;    // batch * 1024
            #pragma unroll
            for (int mt = 0; mt < 4; mt++)
                #pragma unroll
                for (int h = 0; h < 2; h++) {
                    const int rg = wm*64 + 16*mt + qr + 8*h;
                    cwr[2*mt+h] = sCw[p*128 + rg];
                    yrp[2*mt+h] = y_in + (size_t)(base + sNbr[p*128 + rg]) * 128;
                }
        }

        // ---- MMA1: acc = Fij @ Wf1 + bf1 (K=64 padded) ----
        float acc[4][4][4];
        #pragma unroll
        for (int nt = 0; nt < 4; nt++) {
            const float2 bb = *(const float2*)(bf1 + wn*32 + 8*nt + 2*qc);
            #pragma unroll
            for (int mt = 0; mt < 4; mt++) {
                acc[mt][nt][0] = bb.x; acc[mt][nt][1] = bb.y;
                acc[mt][nt][2] = bb.x; acc[mt][nt][3] = bb.y;
            }
        }
        #pragma unroll
        for (int kt = 0; kt < 4; kt++) {
            const int ko = kt*8 + 2*qc;
            uint2 aL[4], aH[4];
            #pragma unroll
            for (int mt = 0; mt < 4; mt++) {
                aL[mt] = *(const uint2*)(smw + A1S + p*5120 + (wm*64 + 16*mt + qr)*40 + ko);
                aH[mt] = *(const uint2*)(smw + A1S + p*5120 + (wm*64 + 16*mt + qr + 8)*40 + ko);
            }
            #pragma unroll
            for (int nt = 0; nt < 4; nt++) {
                const uint2 b = *(const uint2*)(smw + W1S + (wn*32 + 8*nt + qr)*40 + ko);
                #pragma unroll
                for (int mt = 0; mt < 4; mt++)
                    MMA_F16(acc[mt][nt], aL[mt].x, aH[mt].x, aL[mt].y, aH[mt].y, b.x, b.y);
            }
        }
        // ---- H = ssp(acc) -> HHS[p] ----
        #pragma unroll
        for (int mt = 0; mt < 4; mt++)
            #pragma unroll
            for (int nt = 0; nt < 4; nt++) {
                const uint32_t po = pospair((uint32_t)(wn*16 + 4*nt + qc));
                smw[HHS + p*9216 + (wm*64 + 16*mt + qr)*72 + po] =
                    h2(sspf(acc[mt][nt][0]), sspf(acc[mt][nt][1]));
                smw[HHS + p*9216 + (wm*64 + 16*mt + qr + 8)*72 + po] =
                    h2(sspf(acc[mt][nt][2]), sspf(acc[mt][nt][3]));
            }
        // ---- drain prefetch into buf p^1 ----
        if (hasNext) {
            #pragma unroll
            for (int j = 0; j < 13; j++) {
                int idx = gtid + j*128;
                if (idx < 1600) {
                    int row = idx / 25, k2 = idx % 25;
                    smw[A1S + (p^1)*5120 + (wm*64 + row)*40 + pospair(k2)] = h2(pf[j].x, pf[j].y);
                }
            }
            if (gtid < 64) {
                int rg = wm*64 + gtid;
                float c = (nr < 5.0f) ? 0.5f*(cosf(nr*0.62831853071795864769f)+1.0f) : 0.0f;
                sCw[(p^1)*128 + rg]  = c * nm;
                sNbr[(p^1)*128 + rg] = nn;
            }
        }
        asm volatile("bar.sync %0, %1;" :: "r"(barid), "r"(128) : "memory");  // H[p] ready

        // ---- MMA2: acc = H @ Wf2 + bf2 (K=128, W2 in regs) ----
        #pragma unroll
        for (int nt = 0; nt < 4; nt++) {
            const float2 bb = *(const float2*)(bf2 + wn*32 + 8*nt + 2*qc);
            #pragma unroll
            for (int mt = 0; mt < 4; mt++) {
                acc[mt][nt][0] = bb.x; acc[mt][nt][1] = bb.y;
                acc[mt][nt][2] = bb.x; acc[mt][nt][3] = bb.y;
            }
        }
        #pragma unroll
        for (int kt = 0; kt < 8; kt++) {
            const int ko = kt*8 + 2*qc;
            uint2 aL[4], aH[4];
            #pragma unroll
            for (int mt = 0; mt < 4; mt++) {
                aL[mt] = *(const uint2*)(smw + HHS + p*9216 + (wm*64 + 16*mt + qr)*72 + ko);
                aH[mt] = *(const uint2*)(smw + HHS + p*9216 + (wm*64 + 16*mt + qr + 8)*72 + ko);
            }
            #pragma unroll
            for (int nt = 0; nt < 4; nt++)
                #pragma unroll
                for (int mt = 0; mt < 4; mt++)
                    MMA_F16(acc[mt][nt], aL[mt].x, aH[mt].x, aL[mt].y, aH[mt].y,
                            w2f[kt][nt][0], w2f[kt][nt][1]);
        }

        // ---- epilogue: registers only (cwr/yrp); shfl reduce; STG ----
        {
            float s[4][2];
            #pragma unroll
            for (int nt = 0; nt < 4; nt++) { s[nt][0] = 0.f; s[nt][1] = 0.f; }
            #pragma unroll
            for (int mt = 0; mt < 4; mt++)
                #pragma unroll
                for (int h = 0; h < 2; h++) {
                    const float cw = cwr[2*mt+h];
                    const float* yr = yrp[2*mt+h];
                    #pragma unroll
                    for (int nt = 0; nt < 4; nt++) {
                        const float2 yv = *(const float2*)(yr + wn*32 + 8*nt + 2*qc);
                        s[nt][0] += acc[mt][nt][2*h]   * cw * yv.x;
                        s[nt][1] += acc[mt][nt][2*h+1] * cw * yv.y;
                    }
                }
            #pragma unroll
            for (int nt = 0; nt < 4; nt++) {
                #pragma unroll
                for (int m = 4; m <= 16; m <<= 1) {
                    s[nt][0] += __shfl_xor_sync(0xffffffffu, s[nt][0], m);
                    s[nt][1] += __shfl_xor_sync(0xffffffffu, s[nt][1], m);
                }
            }
            if (qr == 0) {
                #pragma unroll
                for (int nt = 0; nt < 4; nt++)
                    *(float2*)(ysum_out + (size_t)(2*it + wm)*128 + wn*32 + 8*nt + 2*qc) =
                        make_float2(s[nt][0], s[nt][1]);
            }
        }
        p ^= 1;   // no second barrier: HHS double-buffered, epi state in regs
    }
}

// ---------------------------------------------------------------------------
extern "C" void kernel_launch(void* const* d_in, const int* in_sizes, int n_in,
                              void* d_out, int out_size)
{
    const float* x       = (const float*)d_in[0];
    const float* r_ij    = (const float*)d_in[1];
    const void*  nbrs    = d_in[2];
    const float* mask    = (const float*)d_in[3];
    const float* f_ij    = (const float*)d_in[4];
    const float* Wf1     = (const float*)d_in[5];
    const float* bf1     = (const float*)d_in[6];
    const float* Wf2     = (const float*)d_in[7];
    const float* bf2     = (const float*)d_in[8];
    const float* W_in2f  = (const float*)d_in[9];
    const float* W_f2out = (const float*)d_in[10];
    const float* b_f2out = (const float*)d_in[11];
    const float* W_dense = (const float*)d_in[12];
    const float* b_dense = (const float*)d_in[13];
    float* out = (float*)d_out;

    float *yp, *ysump;
    cudaGetSymbolAddress((void**)&yp,    g_y);
    cudaGetSymbolAddress((void**)&ysump, g_ysum);

    cudaFuncSetAttribute(in2f_ffma_kernel, cudaFuncAttributeMaxDynamicSharedMemorySize, IN2F_SMEM);
    cudaFuncSetAttribute(tail_tf32_kernel, cudaFuncAttributeMaxDynamicSharedMemorySize, TAIL_SMEM);
    cudaFuncSetAttribute(interaction2_kernel, cudaFuncAttributeMaxDynamicSharedMemorySize, MAIN_SMEM);

    in2f_ffma_kernel<<<ROWS/32, 256, IN2F_SMEM>>>(x, W_in2f, yp, (const int*)nbrs);

    interaction2_kernel<<<148, 256, MAIN_SMEM>>>(r_ij, nbrs, mask, f_ij,
                                                 Wf1, bf1, Wf2, bf2, yp, ysump);

    tail_tf32_kernel<<<ROWS/32, 256, TAIL_SMEM>>>(ysump, W_f2out, b_f2out,
                                                  W_dense, b_dense, out);
}